// round 3
// baseline (speedup 1.0000x reference)
#include <cuda_runtime.h>
#include <math.h>

#define TS 63
#define B 32
#define S 256
#define H 512
#define V 32000
#define G4 2048
typedef unsigned long long ull;

// ------------------------- device scratch -----------------------------------
__device__ float g_h[2][B*H];
__device__ float g_c[2][B*H];
__device__ float g_emb[TS][B*H];
__device__ float g_dec[B*H];       // input_feed / dec_out
__device__ float g_ctx[B*H];
__device__ float g_part0[3][G4*B];
__device__ float g_part1[2][G4*B];
__device__ float g_WaT[H*H];
__device__ float g_sumZ[TS*B];

// ------------------------- f32x2 helpers -------------------------------------
__device__ __forceinline__ ull fma2(ull a, ull b, ull c) {
    ull d; asm("fma.rn.f32x2 %0, %1, %2, %3;" : "=l"(d) : "l"(a), "l"(b), "l"(c));
    return d;
}
__device__ __forceinline__ void unpack2(ull v, float& lo, float& hi) {
    asm("mov.b64 {%0, %1}, %2;" : "=f"(lo), "=f"(hi) : "l"(v));
}

// ------------------------- warp GEMV helpers (LSTM path) ---------------------
__device__ __forceinline__ void warp_gemv_acc(const float* __restrict__ Wrow,
                                              const float* __restrict__ X,
                                              float acc[B]) {
    const int lane = threadIdx.x & 31;
#pragma unroll
    for (int kk = 0; kk < 4; kk++) {
        const int k = kk*128 + lane*4;
        const float4 w = *reinterpret_cast<const float4*>(Wrow + k);
#pragma unroll
        for (int b = 0; b < B; b++) {
            const float4 x = *reinterpret_cast<const float4*>(X + b*H + k);
            acc[b] += w.x*x.x + w.y*x.y + w.z*x.z + w.w*x.w;
        }
    }
}
__device__ __forceinline__ float warp_reduce_b(float acc[B], float* sm) {
    const int lane = threadIdx.x & 31;
#pragma unroll
    for (int b = 0; b < B; b++) sm[b*33 + lane] = acc[b];
    __syncwarp();
    float s = 0.f;
#pragma unroll
    for (int j = 0; j < 32; j++) s += sm[lane*33 + j];
    return s;
}

__device__ __forceinline__ float sigm(float x) { return 1.f/(1.f+expf(-x)); }

// ------------------------- kernels ------------------------------------------
__global__ void __launch_bounds__(256) k_init(const float* __restrict__ eh,
                                              const float* __restrict__ ec,
                                              const float* __restrict__ Wa) {
    int idx = blockIdx.x*256 + threadIdx.x;          // grid covers H*H
    if (idx < 2*B*H) { (&g_h[0][0])[idx] = eh[idx]; (&g_c[0][0])[idx] = ec[idx]; }
    if (idx < B*H)   g_dec[idx] = 0.f;
    if (idx < TS*B)  g_sumZ[idx] = 0.f;
    if (idx < H*H)   { int h = idx / H; int k = idx - h*H; g_WaT[k*H + h] = Wa[idx]; }
}

__global__ void __launch_bounds__(256) k_embed(const int* __restrict__ tgt,
                                               const float* __restrict__ et) {
    int idx = blockIdx.x*256 + threadIdx.x;          // < TS*B*H
    int e = idx & (H - 1);
    int r = idx >> 9;                                 // t*B + b
    int tok = tgt[r];
    (&g_emb[0][0])[idx] = et[(size_t)tok*H + e];
}

__global__ void __launch_bounds__(256) k_gemm0(const float* __restrict__ Wx0,
                                               const float* __restrict__ Wh0, int t) {
    __shared__ float sm[8][33*32];
    const int warp = threadIdx.x >> 5, lane = threadIdx.x & 31;
    const int n = blockIdx.x*8 + warp;                // 0..2047
    const int p = blockIdx.y;                         // 0..2
    const float* Wrow; const float* X;
    if (p == 0)      { Wrow = Wx0 + (size_t)n*1024;        X = g_emb[t]; }
    else if (p == 1) { Wrow = Wx0 + (size_t)n*1024 + 512;  X = g_dec;    }
    else             { Wrow = Wh0 + (size_t)n*512;         X = g_h[0];   }
    float acc[B] = {};
    warp_gemv_acc(Wrow, X, acc);
    float s = warp_reduce_b(acc, sm[warp]);
    g_part0[p][n*B + lane] = s;
}

__global__ void __launch_bounds__(256) k_gemm1(const float* __restrict__ Wx1,
                                               const float* __restrict__ Wh1) {
    __shared__ float sm[8][33*32];
    const int warp = threadIdx.x >> 5, lane = threadIdx.x & 31;
    const int n = blockIdx.x*8 + warp;
    const int p = blockIdx.y;                         // 0..1
    const float* Wrow; const float* X;
    if (p == 0) { Wrow = Wx1 + (size_t)n*512; X = g_h[0]; }
    else        { Wrow = Wh1 + (size_t)n*512; X = g_h[1]; }
    float acc[B] = {};
    warp_gemv_acc(Wrow, X, acc);
    float s = warp_reduce_b(acc, sm[warp]);
    g_part1[p][n*B + lane] = s;
}

// Layer-0 activation (3 partials)
__global__ void __launch_bounds__(256) k_act0(const float* __restrict__ bias) {
    int idx = blockIdx.x*256 + threadIdx.x;           // < B*H
    int b = idx & 31, j = idx >> 5;
    float gi = bias[j], gf = bias[512+j], gg = bias[1024+j], go = bias[1536+j];
#pragma unroll
    for (int p = 0; p < 3; p++) {
        const float* pp = &g_part0[p][0];
        gi += pp[(j       )*B + b];
        gf += pp[(512 + j )*B + b];
        gg += pp[(1024 + j)*B + b];
        go += pp[(1536 + j)*B + b];
    }
    float c  = g_c[0][b*H + j];
    float cn = sigm(gf)*c + sigm(gi)*tanhf(gg);
    g_c[0][b*H + j] = cn;
    g_h[0][b*H + j] = sigm(go)*tanhf(cn);
}

// Fused: layer-1 activation + q projection + attention + context. One block per batch.
__global__ void __launch_bounds__(256) k_attn(const float* __restrict__ mb,
                                              const int* __restrict__ mlen,
                                              const float* __restrict__ b1v,
                                              float* __restrict__ attn_out, int t) {
    __shared__ float sh1[H];
    __shared__ float sq[H];
    __shared__ float al[S];
    __shared__ float red[256];
    const int b = blockIdx.x;
    const int tid = threadIdx.x, warp = tid >> 5, lane = tid & 31;
    const int len = mlen[b];

    // ---- act1 for this batch ----
    for (int j = tid; j < H; j += 256) {
        float gi = b1v[j], gf = b1v[512+j], gg = b1v[1024+j], go = b1v[1536+j];
#pragma unroll
        for (int p = 0; p < 2; p++) {
            const float* pp = &g_part1[p][0];
            gi += pp[(j       )*B + b];
            gf += pp[(512 + j )*B + b];
            gg += pp[(1024 + j)*B + b];
            go += pp[(1536 + j)*B + b];
        }
        float c  = g_c[1][b*H + j];
        float cn = sigm(gf)*c + sigm(gi)*tanhf(gg);
        g_c[1][b*H + j] = cn;
        float hn = sigm(go)*tanhf(cn);
        g_h[1][b*H + j] = hn;
        sh1[j] = hn;
    }
    __syncthreads();

    // ---- q[n] = sum_k h1[k] * Wa[k][n]  (WaT row n = Wa[:,n]) ----
    for (int n = tid; n < H; n += 256) {
        const float4* wr = reinterpret_cast<const float4*>(g_WaT + (size_t)n*H);
        float a = 0.f;
#pragma unroll 8
        for (int k4 = 0; k4 < H/4; k4++) {
            float4 w = wr[k4];
            float4 hx = *reinterpret_cast<const float4*>(sh1 + k4*4);
            a += w.x*hx.x + w.y*hx.y + w.z*hx.z + w.w*hx.w;
        }
        sq[n] = a;
    }
    __syncthreads();

    // ---- alignment scores ----
    for (int s0 = warp; s0 < S; s0 += 8) {
        const float* m = mb + ((size_t)s0*B + b)*H;
        float a = 0.f;
#pragma unroll
        for (int kk = 0; kk < 4; kk++) {
            int k = kk*128 + lane*4;
            float4 mv = *reinterpret_cast<const float4*>(m + k);
            float4 qv = *reinterpret_cast<const float4*>(sq + k);
            a += mv.x*qv.x + mv.y*qv.y + mv.z*qv.z + mv.w*qv.w;
        }
#pragma unroll
        for (int off = 16; off; off >>= 1) a += __shfl_xor_sync(0xffffffffu, a, off);
        if (lane == 0) al[s0] = (s0 < len) ? a : -1.0e9f;
    }
    __syncthreads();

    // ---- softmax over S=256 ----
    float v = al[tid];
    red[tid] = v; __syncthreads();
    for (int o = 128; o; o >>= 1) { if (tid < o) red[tid] = fmaxf(red[tid], red[tid+o]); __syncthreads(); }
    float vmax = red[0];
    __syncthreads();
    float e = expf(v - vmax);
    red[tid] = e; __syncthreads();
    for (int o = 128; o; o >>= 1) { if (tid < o) red[tid] += red[tid+o]; __syncthreads(); }
    float p = e / red[0];
    al[tid] = p;
    attn_out[((size_t)t*B + b)*S + tid] = p;
    __syncthreads();

    // ---- context ----
    for (int k = tid; k < H; k += 256) {
        float acc = 0.f;
#pragma unroll 4
        for (int s = 0; s < S; s++) acc += al[s] * mb[((size_t)s*B + b)*H + k];
        g_ctx[b*H + k] = acc;
    }
}

__global__ void __launch_bounds__(256) k_wc(const float* __restrict__ Wc) {
    __shared__ float sm[8][33*32];
    const int warp = threadIdx.x >> 5, lane = threadIdx.x & 31;
    const int n = blockIdx.x*8 + warp;                // 0..511
    float acc[B] = {};
    warp_gemv_acc(Wc + (size_t)n*1024,       g_ctx,  acc);
    warp_gemv_acc(Wc + (size_t)n*1024 + 512, g_h[1], acc);
    float s = warp_reduce_b(acc, sm[warp]);
    g_dec[lane*H + n] = tanhf(s);
}

// ------------------------- tiled generator GEMM ------------------------------
// C[128 n-tile][32 b] = Wgen_tile (128x512) x dec^T (512x32), f32x2 packed FMA.
#define WS_LD 74                                     // floats per Ws2 row (64 dup + pad)
__global__ void __launch_bounds__(256) k_gen(const float* __restrict__ Wgen,
                                             const float* __restrict__ bgen,
                                             float* __restrict__ out, int t) {
    __shared__ float Ws2[128*WS_LD];                  // W duplicated pairs [n][2k]
    __shared__ float Xs[32*36];                       // X transposed [k][b]
    __shared__ float red[32*33];
    const int tid = threadIdx.x;
    const int bg = tid & 7, ng = tid >> 3;            // compute mapping: 8 b-groups x 32 n-groups
    const int warp = tid >> 5, lane = tid & 31;
    const int ln_off = lane >> 3, lk4 = lane & 7;     // load mapping
    const int nt = blockIdx.x * 128;

    ull acc[4][2] = {};                               // [n_i][b-pair]

    for (int kc = 0; kc < H; kc += 32) {
        __syncthreads();
        // W tile load: warp covers rows warp*16 + i*4 + ln_off
#pragma unroll
        for (int i = 0; i < 4; i++) {
            int n = warp*16 + i*4 + ln_off;
            float4 w4 = *reinterpret_cast<const float4*>(
                Wgen + (size_t)(nt + n)*H + kc + lk4*4);
            float* dst = Ws2 + n*WS_LD + lk4*8;
            *reinterpret_cast<float2*>(dst + 0) = make_float2(w4.x, w4.x);
            *reinterpret_cast<float2*>(dst + 2) = make_float2(w4.y, w4.y);
            *reinterpret_cast<float2*>(dst + 4) = make_float2(w4.z, w4.z);
            *reinterpret_cast<float2*>(dst + 6) = make_float2(w4.w, w4.w);
        }
        // X tile load: thread (b=ng, k4=bg), transpose into Xs[k][b]
        {
            float4 x4 = *reinterpret_cast<const float4*>(g_dec + ng*H + kc + bg*4);
            Xs[(bg*4+0)*36 + ng] = x4.x;
            Xs[(bg*4+1)*36 + ng] = x4.y;
            Xs[(bg*4+2)*36 + ng] = x4.z;
            Xs[(bg*4+3)*36 + ng] = x4.w;
        }
        __syncthreads();
        // compute
#pragma unroll
        for (int k = 0; k < 32; k++) {
            longlong2 xv = *reinterpret_cast<const longlong2*>(Xs + k*36 + bg*4);
            ull x01 = (ull)xv.x, x23 = (ull)xv.y;
#pragma unroll
            for (int i = 0; i < 4; i++) {
                ull w = *reinterpret_cast<const ull*>(Ws2 + (ng*4+i)*WS_LD + 2*k);
                acc[i][0] = fma2(w, x01, acc[i][0]);
                acc[i][1] = fma2(w, x23, acc[i][1]);
            }
        }
    }

    // epilogue: bias, store, exp partial sums
    float sv[4][4];
#pragma unroll
    for (int i = 0; i < 4; i++) {
        float bb = bgen[nt + ng*4 + i];
        unpack2(acc[i][0], sv[i][0], sv[i][1]);
        unpack2(acc[i][1], sv[i][2], sv[i][3]);
        sv[i][0]+=bb; sv[i][1]+=bb; sv[i][2]+=bb; sv[i][3]+=bb;
    }
#pragma unroll
    for (int jb = 0; jb < 4; jb++) {
        int b = bg*4 + jb;
        float4 o4 = make_float4(sv[0][jb], sv[1][jb], sv[2][jb], sv[3][jb]);
        *reinterpret_cast<float4*>(out + ((size_t)(t*B + b))*V + nt + ng*4) = o4;
        float es = expf(sv[0][jb]) + expf(sv[1][jb]) + expf(sv[2][jb]) + expf(sv[3][jb]);
        red[b*33 + ng] = es;
    }
    __syncthreads();
    if (warp == 0) {
        float ssum = 0.f;
#pragma unroll
        for (int j = 0; j < 32; j++) ssum += red[lane*33 + j];
        atomicAdd(&g_sumZ[t*B + lane], ssum);
    }
}

// one pass at the end over all timesteps
__global__ void __launch_bounds__(256) k_lsm(float* __restrict__ out) {
    __shared__ float lz;
    const int t = blockIdx.z, b = blockIdx.y;
    if (threadIdx.x == 0) lz = logf(g_sumZ[t*B + b]);
    __syncthreads();
    int v = blockIdx.x*256 + threadIdx.x;
    out[((size_t)(t*B + b))*V + v] -= lz;
}

// ------------------------- launch -------------------------------------------
extern "C" void kernel_launch(void* const* d_in, const int* in_sizes, int n_in,
                              void* d_out, int out_size) {
    const int*   tgt   = (const int*)  d_in[0];
    const float* mb    = (const float*)d_in[1];
    const int*   mlen  = (const int*)  d_in[2];
    const float* enc_h = (const float*)d_in[3];
    const float* enc_c = (const float*)d_in[4];
    const float* emb   = (const float*)d_in[5];
    const float* Wx0   = (const float*)d_in[6];
    const float* Wh0   = (const float*)d_in[7];
    const float* b0    = (const float*)d_in[8];
    const float* Wx1   = (const float*)d_in[9];
    const float* Wh1   = (const float*)d_in[10];
    const float* b1    = (const float*)d_in[11];
    const float* Wa    = (const float*)d_in[12];
    const float* Wc    = (const float*)d_in[13];
    const float* Wgen  = (const float*)d_in[14];
    const float* bgen  = (const float*)d_in[15];

    float* out      = (float*)d_out;
    float* attn_out = out + (size_t)TS*B*V;

    k_init <<<(H*H + 255)/256, 256>>>(enc_h, enc_c, Wa);
    k_embed<<<(TS*B*H)/256, 256>>>(tgt, emb);

    for (int t = 0; t < TS; t++) {
        k_gemm0<<<dim3(G4/8, 3), 256>>>(Wx0, Wh0, t);
        k_act0 <<<(B*H)/256, 256>>>(b0);
        k_gemm1<<<dim3(G4/8, 2), 256>>>(Wx1, Wh1);
        k_attn <<<B, 256>>>(mb, mlen, b1, attn_out, t);
        k_wc   <<<H/8, 256>>>(Wc);
        k_gen  <<<V/128, 256>>>(Wgen, bgen, out, t);
    }
    k_lsm<<<dim3(V/256, B, TS), 256>>>(out);
}

// round 5
// speedup vs baseline: 1.0446x; 1.0446x over previous
#include <cuda_runtime.h>
#include <cstdint>
#include <math.h>

#define TS 63
#define B 32
#define S 256
#define H 512
#define V 32000
#define G4 2048
typedef unsigned long long ull;

// ------------------------- device scratch -----------------------------------
__device__ float g_h[2][B*H];
__device__ float g_c[2][B*H];
__device__ float g_emb[TS][B*H];
__device__ float g_dec[B*H];        // input_feed / dec_out (b-major)
__device__ float g_decT[H*B];       // dec_out transposed [k][b]
__device__ float g_ctx[B*H];
__device__ float g_part0[3][G4*B];
__device__ float g_part1[2][G4*B];
__device__ float g_WaT[H*H];
__device__ float g_sumZ[TS*B];

// ------------------------- f32x2 / cp.async helpers --------------------------
__device__ __forceinline__ ull fma2(ull a, ull b, ull c) {
    ull d; asm("fma.rn.f32x2 %0, %1, %2, %3;" : "=l"(d) : "l"(a), "l"(b), "l"(c));
    return d;
}
__device__ __forceinline__ ull dup2(float x) {
    ull d; asm("mov.b64 %0, {%1, %1};" : "=l"(d) : "f"(x));
    return d;
}
__device__ __forceinline__ void unpack2(ull v, float& lo, float& hi) {
    asm("mov.b64 {%0, %1}, %2;" : "=f"(lo), "=f"(hi) : "l"(v));
}
__device__ __forceinline__ void cp8(uint32_t dst, const void* src) {
    asm volatile("cp.async.ca.shared.global [%0], [%1], 8;" :: "r"(dst), "l"(src));
}
__device__ __forceinline__ void cp_commit() {
    asm volatile("cp.async.commit_group;");
}
template <int N>
__device__ __forceinline__ void cp_wait() {
    asm volatile("cp.async.wait_group %0;" :: "n"(N));
}

// ------------------------- warp GEMV helpers (LSTM path) ---------------------
__device__ __forceinline__ void warp_gemv_acc(const float* __restrict__ Wrow,
                                              const float* __restrict__ X,
                                              float acc[B]) {
    const int lane = threadIdx.x & 31;
#pragma unroll
    for (int kk = 0; kk < 4; kk++) {
        const int k = kk*128 + lane*4;
        const float4 w = *reinterpret_cast<const float4*>(Wrow + k);
#pragma unroll
        for (int b = 0; b < B; b++) {
            const float4 x = *reinterpret_cast<const float4*>(X + b*H + k);
            acc[b] += w.x*x.x + w.y*x.y + w.z*x.z + w.w*x.w;
        }
    }
}
__device__ __forceinline__ float warp_reduce_b(float acc[B], float* sm) {
    const int lane = threadIdx.x & 31;
#pragma unroll
    for (int b = 0; b < B; b++) sm[b*33 + lane] = acc[b];
    __syncwarp();
    float s = 0.f;
#pragma unroll
    for (int j = 0; j < 32; j++) s += sm[lane*33 + j];
    return s;
}

__device__ __forceinline__ float sigm(float x) { return 1.f/(1.f+expf(-x)); }

// ------------------------- kernels ------------------------------------------
__global__ void __launch_bounds__(256) k_init(const float* __restrict__ eh,
                                              const float* __restrict__ ec,
                                              const float* __restrict__ Wa) {
    int idx = blockIdx.x*256 + threadIdx.x;          // grid covers H*H
    if (idx < 2*B*H) { (&g_h[0][0])[idx] = eh[idx]; (&g_c[0][0])[idx] = ec[idx]; }
    if (idx < B*H)   { g_dec[idx] = 0.f; g_decT[idx] = 0.f; }
    if (idx < TS*B)  g_sumZ[idx] = 0.f;
    if (idx < H*H)   { int h = idx / H; int k = idx - h*H; g_WaT[k*H + h] = Wa[idx]; }
}

__global__ void __launch_bounds__(256) k_embed(const int* __restrict__ tgt,
                                               const float* __restrict__ et) {
    int idx = blockIdx.x*256 + threadIdx.x;          // < TS*B*H
    int e = idx & (H - 1);
    int r = idx >> 9;                                 // t*B + b
    int tok = tgt[r];
    (&g_emb[0][0])[idx] = et[(size_t)tok*H + e];
}

__global__ void __launch_bounds__(256) k_gemm0(const float* __restrict__ Wx0,
                                               const float* __restrict__ Wh0, int t) {
    __shared__ float sm[8][33*32];
    const int warp = threadIdx.x >> 5, lane = threadIdx.x & 31;
    const int n = blockIdx.x*8 + warp;                // 0..2047
    const int p = blockIdx.y;                         // 0..2
    const float* Wrow; const float* X;
    if (p == 0)      { Wrow = Wx0 + (size_t)n*1024;        X = g_emb[t]; }
    else if (p == 1) { Wrow = Wx0 + (size_t)n*1024 + 512;  X = g_dec;    }
    else             { Wrow = Wh0 + (size_t)n*512;         X = g_h[0];   }
    float acc[B] = {};
    warp_gemv_acc(Wrow, X, acc);
    float s = warp_reduce_b(acc, sm[warp]);
    g_part0[p][n*B + lane] = s;
}

__global__ void __launch_bounds__(256) k_gemm1(const float* __restrict__ Wx1,
                                               const float* __restrict__ Wh1) {
    __shared__ float sm[8][33*32];
    const int warp = threadIdx.x >> 5, lane = threadIdx.x & 31;
    const int n = blockIdx.x*8 + warp;
    const int p = blockIdx.y;                         // 0..1
    const float* Wrow; const float* X;
    if (p == 0) { Wrow = Wx1 + (size_t)n*512; X = g_h[0]; }
    else        { Wrow = Wh1 + (size_t)n*512; X = g_h[1]; }
    float acc[B] = {};
    warp_gemv_acc(Wrow, X, acc);
    float s = warp_reduce_b(acc, sm[warp]);
    g_part1[p][n*B + lane] = s;
}

// Layer-0 activation (3 partials)
__global__ void __launch_bounds__(256) k_act0(const float* __restrict__ bias) {
    int idx = blockIdx.x*256 + threadIdx.x;           // < B*H
    int b = idx & 31, j = idx >> 5;
    float gi = bias[j], gf = bias[512+j], gg = bias[1024+j], go = bias[1536+j];
#pragma unroll
    for (int p = 0; p < 3; p++) {
        const float* pp = &g_part0[p][0];
        gi += pp[(j       )*B + b];
        gf += pp[(512 + j )*B + b];
        gg += pp[(1024 + j)*B + b];
        go += pp[(1536 + j)*B + b];
    }
    float c  = g_c[0][b*H + j];
    float cn = sigm(gf)*c + sigm(gi)*tanhf(gg);
    g_c[0][b*H + j] = cn;
    g_h[0][b*H + j] = sigm(go)*tanhf(cn);
}

// Fused: layer-1 activation + q projection + attention + context. One block per batch.
__global__ void __launch_bounds__(256) k_attn(const float* __restrict__ mb,
                                              const int* __restrict__ mlen,
                                              const float* __restrict__ b1v,
                                              float* __restrict__ attn_out, int t) {
    __shared__ float sh1[H];
    __shared__ float sq[H];
    __shared__ float al[S];
    __shared__ float red[256];
    const int b = blockIdx.x;
    const int tid = threadIdx.x, warp = tid >> 5, lane = tid & 31;
    const int len = mlen[b];

    // ---- act1 for this batch ----
    for (int j = tid; j < H; j += 256) {
        float gi = b1v[j], gf = b1v[512+j], gg = b1v[1024+j], go = b1v[1536+j];
#pragma unroll
        for (int p = 0; p < 2; p++) {
            const float* pp = &g_part1[p][0];
            gi += pp[(j       )*B + b];
            gf += pp[(512 + j )*B + b];
            gg += pp[(1024 + j)*B + b];
            go += pp[(1536 + j)*B + b];
        }
        float c  = g_c[1][b*H + j];
        float cn = sigm(gf)*c + sigm(gi)*tanhf(gg);
        g_c[1][b*H + j] = cn;
        float hn = sigm(go)*tanhf(cn);
        g_h[1][b*H + j] = hn;
        sh1[j] = hn;
    }
    __syncthreads();

    // ---- q[n] = sum_k h1[k] * Wa[k][n] ----
    for (int n = tid; n < H; n += 256) {
        const float4* wr = reinterpret_cast<const float4*>(g_WaT + (size_t)n*H);
        float a = 0.f;
#pragma unroll 8
        for (int k4 = 0; k4 < H/4; k4++) {
            float4 w = wr[k4];
            float4 hx = *reinterpret_cast<const float4*>(sh1 + k4*4);
            a += w.x*hx.x + w.y*hx.y + w.z*hx.z + w.w*hx.w;
        }
        sq[n] = a;
    }
    __syncthreads();

    // ---- alignment scores ----
    for (int s0 = warp; s0 < S; s0 += 8) {
        const float* m = mb + ((size_t)s0*B + b)*H;
        float a = 0.f;
#pragma unroll
        for (int kk = 0; kk < 4; kk++) {
            int k = kk*128 + lane*4;
            float4 mv = *reinterpret_cast<const float4*>(m + k);
            float4 qv = *reinterpret_cast<const float4*>(sq + k);
            a += mv.x*qv.x + mv.y*qv.y + mv.z*qv.z + mv.w*qv.w;
        }
#pragma unroll
        for (int off = 16; off; off >>= 1) a += __shfl_xor_sync(0xffffffffu, a, off);
        if (lane == 0) al[s0] = (s0 < len) ? a : -1.0e9f;
    }
    __syncthreads();

    // ---- softmax over S=256 ----
    float v = al[tid];
    red[tid] = v; __syncthreads();
    for (int o = 128; o; o >>= 1) { if (tid < o) red[tid] = fmaxf(red[tid], red[tid+o]); __syncthreads(); }
    float vmax = red[0];
    __syncthreads();
    float e = expf(v - vmax);
    red[tid] = e; __syncthreads();
    for (int o = 128; o; o >>= 1) { if (tid < o) red[tid] += red[tid+o]; __syncthreads(); }
    float p = e / red[0];
    al[tid] = p;
    attn_out[((size_t)t*B + b)*S + tid] = p;
    __syncthreads();

    // ---- context ----
    for (int k = tid; k < H; k += 256) {
        float acc = 0.f;
#pragma unroll 4
        for (int s = 0; s < S; s++) acc += al[s] * mb[((size_t)s*B + b)*H + k];
        g_ctx[b*H + k] = acc;
    }
}

__global__ void __launch_bounds__(256) k_wc(const float* __restrict__ Wc) {
    __shared__ float sm[8][33*32];
    const int warp = threadIdx.x >> 5, lane = threadIdx.x & 31;
    const int n = blockIdx.x*8 + warp;                // 0..511
    float acc[B] = {};
    warp_gemv_acc(Wc + (size_t)n*1024,       g_ctx,  acc);
    warp_gemv_acc(Wc + (size_t)n*1024 + 512, g_h[1], acc);
    float s = warp_reduce_b(acc, sm[warp]);
    float d = tanhf(s);
    g_dec [lane*H + n] = d;
    g_decT[n*B + lane] = d;                           // transposed copy for k_gen
}

// ------------------------- generator GEMM (register-blocked f32x2) -----------
// Block = 128 threads computes C[128 n][32 b]. Thread (ng=tid>>3, bg=tid&7)
// owns 8n x 4b. W staged via cp.async in XOR-swizzled 8B granules, X from
// g_decT (k-major, b-pairs contiguous). Double-buffered over 16 k-chunks of 32.
__global__ void __launch_bounds__(128) k_gen(const float* __restrict__ Wgen,
                                             const float* __restrict__ bgen,
                                             float* __restrict__ out, int t) {
    __shared__ float2 Ws[2][128*16];                  // [buf][n*16 + (k2 ^ (n>>3))]
    __shared__ float2 Xs[2][32*17];                   // [buf][k*17 + b/2]
    __shared__ float red[32*17];

    const int tid = threadIdx.x;
    const int bg = tid & 7, ng = tid >> 3;            // 8 bgroups x 16 ngroups
    const int nt = blockIdx.x * 128;

    const uint32_t wsBase0 = (uint32_t)__cvta_generic_to_shared(&Ws[0][0]);
    const uint32_t wsBase1 = (uint32_t)__cvta_generic_to_shared(&Ws[1][0]);
    const uint32_t xsBase0 = (uint32_t)__cvta_generic_to_shared(&Xs[0][0]);
    const uint32_t xsBase1 = (uint32_t)__cvta_generic_to_shared(&Xs[1][0]);

    const float2* wsrc_base = reinterpret_cast<const float2*>(Wgen) + (size_t)nt*256;
    const float2* xsrc_base = reinterpret_cast<const float2*>(g_decT);

    // prefetch lambda (chunk c into buffer buf)
    auto prefetch = [&](int c, int buf) {
        const uint32_t wb = buf ? wsBase1 : wsBase0;
        const uint32_t xb = buf ? xsBase1 : xsBase0;
        const int r = tid >> 3, g0 = (tid & 7) * 2;
#pragma unroll
        for (int p = 0; p < 8; p++) {
            int n = p*16 + r;
            const float2* src = wsrc_base + (size_t)n*256 + c*16 + g0;
            int sw = n >> 3;
            cp8(wb + (uint32_t)(n*16 + (g0     ^ sw))*8, src);
            cp8(wb + (uint32_t)(n*16 + ((g0+1) ^ sw))*8, src + 1);
        }
#pragma unroll
        for (int j = 0; j < 4; j++) {
            int idx = tid*4 + j;                      // 0..511
            int k = idx >> 4, bp = idx & 15;
            cp8(xb + (uint32_t)(k*17 + bp)*8, xsrc_base + (size_t)(c*32 + k)*16 + bp);
        }
        cp_commit();
    };

    ull acc[8][2] = {};                               // [n_i][b-pair(0:b01,1:b23)]

    prefetch(0, 0);
    prefetch(1, 1);

    for (int c = 0; c < 16; c++) {
        if (c < 14) cp_wait<1>(); else cp_wait<0>();
        __syncthreads();
        const int buf = c & 1;
        const float2* W = &Ws[buf][0];
        const float2* X = &Xs[buf][0];
#pragma unroll 4
        for (int k2 = 0; k2 < 16; k2++) {             // k pair = (2k2, 2k2+1)
            const int k0 = 2*k2, k1 = 2*k2 + 1;
            ull xA0 = *reinterpret_cast<const ull*>(X + k0*17 + bg*2);
            ull xA1 = *reinterpret_cast<const ull*>(X + k0*17 + bg*2 + 1);
            ull xB0 = *reinterpret_cast<const ull*>(X + k1*17 + bg*2);
            ull xB1 = *reinterpret_cast<const ull*>(X + k1*17 + bg*2 + 1);
#pragma unroll
            for (int i = 0; i < 8; i++) {
                float2 w = W[(ng*8 + i)*16 + (k2 ^ ng)];
                ull wA = dup2(w.x), wB = dup2(w.y);
                acc[i][0] = fma2(wA, xA0, acc[i][0]);
                acc[i][1] = fma2(wA, xA1, acc[i][1]);
                acc[i][0] = fma2(wB, xB0, acc[i][0]);
                acc[i][1] = fma2(wB, xB1, acc[i][1]);
            }
        }
        __syncthreads();
        if (c + 2 < 16) prefetch(c + 2, buf);
    }

    // ---- epilogue: bias, store logits, fused exp-sum ----
    float sv[8][4];
#pragma unroll
    for (int i = 0; i < 8; i++) {
        float bb = bgen[nt + ng*8 + i];
        unpack2(acc[i][0], sv[i][0], sv[i][1]);
        unpack2(acc[i][1], sv[i][2], sv[i][3]);
        sv[i][0]+=bb; sv[i][1]+=bb; sv[i][2]+=bb; sv[i][3]+=bb;
    }
#pragma unroll
    for (int jb = 0; jb < 4; jb++) {
        int b = bg*4 + jb;
        float* orow = out + ((size_t)(t*B + b))*V + nt + ng*8;
        float4 o0 = make_float4(sv[0][jb], sv[1][jb], sv[2][jb], sv[3][jb]);
        float4 o1 = make_float4(sv[4][jb], sv[5][jb], sv[6][jb], sv[7][jb]);
        *reinterpret_cast<float4*>(orow)     = o0;
        *reinterpret_cast<float4*>(orow + 4) = o1;
        float es = expf(sv[0][jb]) + expf(sv[1][jb]) + expf(sv[2][jb]) + expf(sv[3][jb])
                 + expf(sv[4][jb]) + expf(sv[5][jb]) + expf(sv[6][jb]) + expf(sv[7][jb]);
        red[b*17 + ng] = es;
    }
    __syncthreads();
    if (tid < 32) {
        float ssum = 0.f;
#pragma unroll
        for (int j = 0; j < 16; j++) ssum += red[tid*17 + j];
        atomicAdd(&g_sumZ[t*B + tid], ssum);
    }
}

// one pass at the end over all timesteps
__global__ void __launch_bounds__(256) k_lsm(float* __restrict__ out) {
    __shared__ float lz;
    const int t = blockIdx.z, b = blockIdx.y;
    if (threadIdx.x == 0) lz = logf(g_sumZ[t*B + b]);
    __syncthreads();
    int v = blockIdx.x*256 + threadIdx.x;
    out[((size_t)(t*B + b))*V + v] -= lz;
}

// ------------------------- launch -------------------------------------------
extern "C" void kernel_launch(void* const* d_in, const int* in_sizes, int n_in,
                              void* d_out, int out_size) {
    const int*   tgt   = (const int*)  d_in[0];
    const float* mb    = (const float*)d_in[1];
    const int*   mlen  = (const int*)  d_in[2];
    const float* enc_h = (const float*)d_in[3];
    const float* enc_c = (const float*)d_in[4];
    const float* emb   = (const float*)d_in[5];
    const float* Wx0   = (const float*)d_in[6];
    const float* Wh0   = (const float*)d_in[7];
    const float* b0    = (const float*)d_in[8];
    const float* Wx1   = (const float*)d_in[9];
    const float* Wh1   = (const float*)d_in[10];
    const float* b1    = (const float*)d_in[11];
    const float* Wa    = (const float*)d_in[12];
    const float* Wc    = (const float*)d_in[13];
    const float* Wgen  = (const float*)d_in[14];
    const float* bgen  = (const float*)d_in[15];

    float* out      = (float*)d_out;
    float* attn_out = out + (size_t)TS*B*V;

    k_init <<<(H*H + 255)/256, 256>>>(enc_h, enc_c, Wa);
    k_embed<<<(TS*B*H)/256, 256>>>(tgt, emb);

    for (int t = 0; t < TS; t++) {
        k_gemm0<<<dim3(G4/8, 3), 256>>>(Wx0, Wh0, t);
        k_act0 <<<(B*H)/256, 256>>>(b0);
        k_gemm1<<<dim3(G4/8, 2), 256>>>(Wx1, Wh1);
        k_attn <<<B, 256>>>(mb, mlen, b1, attn_out, t);
        k_wc   <<<H/8, 256>>>(Wc);
        k_gen  <<<V/128, 128>>>(Wgen, bgen, out, t);
    }
    k_lsm<<<dim3(V/256, B, TS), 256>>>(out);
}